// round 3
// baseline (speedup 1.0000x reference)
#include <cuda_runtime.h>
#include <math.h>

// ---------------------------------------------------------------------------
// PGA(3,0,1) blade algebra, computed at compile time.
// Blade index order (matches reference BLADES):
//  0:()  1:e0  2:e1  3:e2  4:e3  5:e01 6:e02 7:e03 8:e12 9:e13 10:e23
//  11:e012 12:e013 13:e023 14:e123 15:e0123
// Bitmask representation: bit b set <=> generator e_b present.
// ---------------------------------------------------------------------------

__host__ __device__ constexpr int pc4(int x) {
    return ((x >> 0) & 1) + ((x >> 1) & 1) + ((x >> 2) & 1) + ((x >> 3) & 1);
}

__host__ __device__ constexpr int I2M(int i) {
    return (i == 0) ? 0  : (i == 1) ? 1  : (i == 2) ? 2  : (i == 3) ? 4  :
           (i == 4) ? 8  : (i == 5) ? 3  : (i == 6) ? 5  : (i == 7) ? 9  :
           (i == 8) ? 6  : (i == 9) ? 10 : (i == 10) ? 12 : (i == 11) ? 7 :
           (i == 12) ? 11 : (i == 13) ? 13 : (i == 14) ? 14 : 15;
}

__host__ __device__ constexpr int M2I(int m) {
    return (m == 0) ? 0  : (m == 1) ? 1  : (m == 2) ? 2  : (m == 3) ? 5  :
           (m == 4) ? 3  : (m == 5) ? 6  : (m == 6) ? 8  : (m == 7) ? 11 :
           (m == 8) ? 4  : (m == 9) ? 7  : (m == 10) ? 9 : (m == 11) ? 12 :
           (m == 12) ? 10 : (m == 13) ? 13 : (m == 14) ? 14 : 15;
}

__host__ __device__ constexpr int msign(int a, int b) {
    int s = 0;
    if ((b >> 0) & 1) s += pc4(a >> 1);
    if ((b >> 1) & 1) s += pc4(a >> 2);
    if ((b >> 2) & 1) s += pc4(a >> 3);
    return (s & 1) ? -1 : 1;
}

__host__ __device__ constexpr int dsign(int m) { return msign(m, 15 ^ m); }

// join sign for blade pair (ma, mb) with ma|mb == 15
__host__ __device__ constexpr int jsign(int ma, int mb) {
    return dsign(ma) * dsign(mb) * msign(15 ^ ma, 15 ^ mb) * dsign(ma & mb);
}

// ---------------------------------------------------------------------------
// One thread per 16-component token. Register budget is hard-capped at 64 by
// the build, so the bilinear stage is structured j-outer/i-inner with xg[j]
// recomputed on the fly: peak live set = xn[16]+gp[16]+jn[16]+~10 scalars.
// ---------------------------------------------------------------------------
__global__ void __launch_bounds__(128)
mvffn_kernel(const float* __restrict__ x,
             const float* __restrict__ w1, const float* __restrict__ v1, const float* __restrict__ b1,
             const float* __restrict__ wg, const float* __restrict__ vg, const float* __restrict__ bg,
             const float* __restrict__ wj, const float* __restrict__ vj, const float* __restrict__ bj,
             float* __restrict__ out, int ntok)
{
    int t = blockIdx.x * blockDim.x + threadIdx.x;
    if (t >= ntok) return;

    const float4* xin = reinterpret_cast<const float4*>(x) + (size_t)t * 4;
    float4 q0 = xin[0], q1 = xin[1], q2 = xin[2], q3 = xin[3];

    float xn[16] = { q0.x, q0.y, q0.z, q0.w,
                     q1.x, q1.y, q1.z, q1.w,
                     q2.x, q2.y, q2.z, q2.w,
                     q3.x, q3.y, q3.z, q3.w };

    // ---- normalize over non-e0 blades: idx 0,2,3,4,8,9,10,14 ----
    float s = 1e-5f;
    s = fmaf(xn[0],  xn[0],  s);
    s = fmaf(xn[2],  xn[2],  s);
    s = fmaf(xn[3],  xn[3],  s);
    s = fmaf(xn[4],  xn[4],  s);
    s = fmaf(xn[8],  xn[8],  s);
    s = fmaf(xn[9],  xn[9],  s);
    s = fmaf(xn[10], xn[10], s);
    s = fmaf(xn[14], xn[14], s);
    float rinv = rsqrtf(s);
    float nrm  = s * rinv;     // sqrt(s): recompute original x = xn*nrm
    #pragma unroll
    for (int d = 0; d < 16; d++) xn[d] *= rinv;

    // ---- first linear's weights, gate, fold gate into them ----
    const float4 w1a = *reinterpret_cast<const float4*>(w1);
    const float  w1b = w1[4];
    const float4 v1a = *reinterpret_cast<const float4*>(v1);

    float xp0  = fmaf(w1a.x, xn[0], b1[0]);       // pre-gate scalar component
    float gate = xp0 * normcdff(xp0);             // exact GELU

    const float W1[5] = { gate * w1a.x, gate * w1a.y, gate * w1a.z,
                          gate * w1a.w, gate * w1b };
    const float V1[4] = { gate * v1a.x, gate * v1a.y, gate * v1a.z, gate * v1a.w };
    const float xg0   = gate * xp0;               // xg[0] (includes bias)

    // ---- geometric product + join, j-outer / i-inner with xg[j] recomputed
    //      on the fly (no xg[16] array -> no spills at 64 regs) ----
    float gp[16], jn[16];
    #pragma unroll
    for (int k = 0; k < 16; k++) { gp[k] = 0.f; jn[k] = 0.f; }

    #pragma unroll
    for (int j = 0; j < 16; j++) {
        const int mb = I2M(j);
        const int gB = pc4(mb);

        float xgj;
        if (j == 0) {
            xgj = xg0;
        } else {
            xgj = W1[gB] * xn[j];
            if ((mb & 1) && gB < 4) xgj = fmaf(V1[gB], xn[M2I(mb ^ 1)], xgj);
        }

        #pragma unroll
        for (int i = 0; i < 16; i++) {
            const int ma = I2M(i);
            // geometric product: zero iff both blades contain e0 (e0^2 = 0)
            if (!(ma & mb & 1)) {
                const int k = M2I(ma ^ mb);
                if (msign(ma, mb) > 0) gp[k] = fmaf(xn[i],  xgj, gp[k]);
                else                   gp[k] = fmaf(xn[i], -xgj, gp[k]);
            }
            // join: nonzero iff ma|mb == 15, target ma&mb
            if ((ma | mb) == 15) {
                const int k = M2I(ma & mb);
                if (jsign(ma, mb) > 0) jn[k] = fmaf(xn[i],  xgj, jn[k]);
                else                   jn[k] = fmaf(xn[i], -xgj, jn[k]);
            }
        }
    }

    // ---- output linears (x15 folded into join weights) + residual ----
    const float4 wga = *reinterpret_cast<const float4*>(wg);
    const float  wgb = wg[4];
    const float4 vga = *reinterpret_cast<const float4*>(vg);
    const float4 wja = *reinterpret_cast<const float4*>(wj);
    const float  wjb = wj[4];
    const float4 vja = *reinterpret_cast<const float4*>(vj);

    const float x15 = xn[15];
    const float WG[5] = { wga.x, wga.y, wga.z, wga.w, wgb };
    const float VG[4] = { vga.x, vga.y, vga.z, vga.w };
    const float WJ[5] = { wja.x * x15, wja.y * x15, wja.z * x15, wja.w * x15, wjb * x15 };
    const float VJ[4] = { vja.x * x15, vja.y * x15, vja.z * x15, vja.w * x15 };

    float o[16];
    #pragma unroll
    for (int d = 0; d < 16; d++) {
        const int m = I2M(d);
        const int g = pc4(m);
        float v = xn[d] * nrm;               // residual: original x[d]
        v = fmaf(WG[g], gp[d], v);
        v = fmaf(WJ[g], jn[d], v);
        if ((m & 1) && g < 4) {
            const int sidx = M2I(m ^ 1);
            v = fmaf(VG[g], gp[sidx], v);
            v = fmaf(VJ[g], jn[sidx], v);
        }
        o[d] = v;
    }
    o[0] += bg[0] + bj[0];

    float4* op = reinterpret_cast<float4*>(out) + (size_t)t * 4;
    op[0] = make_float4(o[0],  o[1],  o[2],  o[3]);
    op[1] = make_float4(o[4],  o[5],  o[6],  o[7]);
    op[2] = make_float4(o[8],  o[9],  o[10], o[11]);
    op[3] = make_float4(o[12], o[13], o[14], o[15]);
}

extern "C" void kernel_launch(void* const* d_in, const int* in_sizes, int n_in,
                              void* d_out, int out_size)
{
    const float* x  = (const float*)d_in[0];
    const float* w1 = (const float*)d_in[1];
    const float* v1 = (const float*)d_in[2];
    const float* b1 = (const float*)d_in[3];
    const float* wg = (const float*)d_in[4];
    const float* vg = (const float*)d_in[5];
    const float* bg = (const float*)d_in[6];
    const float* wj = (const float*)d_in[7];
    const float* vj = (const float*)d_in[8];
    const float* bj = (const float*)d_in[9];

    const int ntok = in_sizes[0] / 16;
    const int threads = 128;
    const int blocks  = (ntok + threads - 1) / threads;

    mvffn_kernel<<<blocks, threads>>>(x, w1, v1, b1, wg, vg, bg, wj, vj, bj,
                                      (float*)d_out, ntok);
}

// round 4
// speedup vs baseline: 1.0201x; 1.0201x over previous
#include <cuda_runtime.h>
#include <math.h>

// ---------------------------------------------------------------------------
// PGA(3,0,1) blade algebra, computed at compile time.
// Blade index order (matches reference BLADES):
//  0:()  1:e0  2:e1  3:e2  4:e3  5:e01 6:e02 7:e03 8:e12 9:e13 10:e23
//  11:e012 12:e013 13:e023 14:e123 15:e0123
// ---------------------------------------------------------------------------

__host__ __device__ constexpr int pc4(int x) {
    return ((x >> 0) & 1) + ((x >> 1) & 1) + ((x >> 2) & 1) + ((x >> 3) & 1);
}

__host__ __device__ constexpr int I2M(int i) {
    return (i == 0) ? 0  : (i == 1) ? 1  : (i == 2) ? 2  : (i == 3) ? 4  :
           (i == 4) ? 8  : (i == 5) ? 3  : (i == 6) ? 5  : (i == 7) ? 9  :
           (i == 8) ? 6  : (i == 9) ? 10 : (i == 10) ? 12 : (i == 11) ? 7 :
           (i == 12) ? 11 : (i == 13) ? 13 : (i == 14) ? 14 : 15;
}

__host__ __device__ constexpr int M2I(int m) {
    return (m == 0) ? 0  : (m == 1) ? 1  : (m == 2) ? 2  : (m == 3) ? 5  :
           (m == 4) ? 3  : (m == 5) ? 6  : (m == 6) ? 8  : (m == 7) ? 11 :
           (m == 8) ? 4  : (m == 9) ? 7  : (m == 10) ? 9 : (m == 11) ? 12 :
           (m == 12) ? 10 : (m == 13) ? 13 : (m == 14) ? 14 : 15;
}

__host__ __device__ constexpr int msign(int a, int b) {
    int s = 0;
    if ((b >> 0) & 1) s += pc4(a >> 1);
    if ((b >> 1) & 1) s += pc4(a >> 2);
    if ((b >> 2) & 1) s += pc4(a >> 3);
    return (s & 1) ? -1 : 1;
}

__host__ __device__ constexpr int dsign(int m) { return msign(m, 15 ^ m); }

__host__ __device__ constexpr int jsign(int ma, int mb) {
    return dsign(ma) * dsign(mb) * msign(15 ^ ma, 15 ^ mb) * dsign(ma & mb);
}

// ---------------------------------------------------------------------------
// Block of 256 threads handles 256 tokens (16 KB). Global I/O is fully
// coalesced through a swizzled smem staging buffer; one thread computes one
// token from registers.
//
// Swizzle: token t, chunk c (float4 units) lives at smem4[4t + (c ^ ((t>>1)&3))].
//  - coalesced STS.128 / LDS.128 phases: consecutive f map to distinct 16B
//    bank groups within each 8-thread phase (swizzle preserves f>>2).
//  - per-token LDS.128/STS.128: group = (4t + c') mod 8; threads of equal
//    parity within a phase get distinct c' via ((t>>1)&3) -> conflict-free.
// ---------------------------------------------------------------------------
#define TOK_PER_BLK 256

__device__ __forceinline__ int swz(int t, int c) {
    return 4 * t + (c ^ ((t >> 1) & 3));
}

__global__ void __launch_bounds__(TOK_PER_BLK)
mvffn_kernel(const float* __restrict__ x,
             const float* __restrict__ w1, const float* __restrict__ v1, const float* __restrict__ b1,
             const float* __restrict__ wg, const float* __restrict__ vg, const float* __restrict__ bg,
             const float* __restrict__ wj, const float* __restrict__ vj, const float* __restrict__ bj,
             float* __restrict__ out, int ntok)
{
    __shared__ float4 stage[TOK_PER_BLK * 4];

    const int tid  = threadIdx.x;
    const int base = blockIdx.x * TOK_PER_BLK;          // first token of block
    const float4* xin4  = reinterpret_cast<const float4*>(x)   + (size_t)base * 4;
    float4*       out4  = reinterpret_cast<float4*>(out)       + (size_t)base * 4;
    const int     nf4   = min(TOK_PER_BLK, ntok - base) * 4;   // float4s this block

    // ---- coalesced load -> swizzled smem ----
    #pragma unroll
    for (int k = 0; k < 4; k++) {
        int f = tid + k * TOK_PER_BLK;
        if (f < nf4) {
            int t = f >> 2, c = f & 3;
            stage[swz(t, c)] = xin4[f];
        }
    }
    __syncthreads();

    const int t = base + tid;
    float o[16];

    if (t < ntok) {
        float4 q0 = stage[swz(tid, 0)];
        float4 q1 = stage[swz(tid, 1)];
        float4 q2 = stage[swz(tid, 2)];
        float4 q3 = stage[swz(tid, 3)];

        float xn[16] = { q0.x, q0.y, q0.z, q0.w,
                         q1.x, q1.y, q1.z, q1.w,
                         q2.x, q2.y, q2.z, q2.w,
                         q3.x, q3.y, q3.z, q3.w };

        // ---- normalize over non-e0 blades: idx 0,2,3,4,8,9,10,14 ----
        float s = 1e-5f;
        s = fmaf(xn[0],  xn[0],  s);
        s = fmaf(xn[2],  xn[2],  s);
        s = fmaf(xn[3],  xn[3],  s);
        s = fmaf(xn[4],  xn[4],  s);
        s = fmaf(xn[8],  xn[8],  s);
        s = fmaf(xn[9],  xn[9],  s);
        s = fmaf(xn[10], xn[10], s);
        s = fmaf(xn[14], xn[14], s);
        float rinv = rsqrtf(s);
        float nrm  = s * rinv;     // sqrt(s): recompute original x = xn*nrm
        #pragma unroll
        for (int d = 0; d < 16; d++) xn[d] *= rinv;

        // ---- first linear's weights, gate, fold gate into them ----
        const float4 w1a = *reinterpret_cast<const float4*>(w1);
        const float  w1b = w1[4];
        const float4 v1a = *reinterpret_cast<const float4*>(v1);

        float xp0  = fmaf(w1a.x, xn[0], b1[0]);       // pre-gate scalar comp
        float gate = xp0 * normcdff(xp0);             // exact GELU

        const float W1[5] = { gate * w1a.x, gate * w1a.y, gate * w1a.z,
                              gate * w1a.w, gate * w1b };
        const float V1[4] = { gate * v1a.x, gate * v1a.y, gate * v1a.z, gate * v1a.w };
        const float xg0   = gate * xp0;               // xg[0] (bias included)

        // ---- geometric product + join, j-outer / i-inner, xg[j] on the fly ----
        float gp[16], jn[16];
        #pragma unroll
        for (int k = 0; k < 16; k++) { gp[k] = 0.f; jn[k] = 0.f; }

        #pragma unroll
        for (int j = 0; j < 16; j++) {
            const int mb = I2M(j);
            const int gB = pc4(mb);

            float xgj;
            if (j == 0) {
                xgj = xg0;
            } else {
                xgj = W1[gB] * xn[j];
                if ((mb & 1) && gB < 4) xgj = fmaf(V1[gB], xn[M2I(mb ^ 1)], xgj);
            }

            #pragma unroll
            for (int i = 0; i < 16; i++) {
                const int ma = I2M(i);
                if (!(ma & mb & 1)) {                  // e0^2 = 0
                    const int k = M2I(ma ^ mb);
                    if (msign(ma, mb) > 0) gp[k] = fmaf(xn[i],  xgj, gp[k]);
                    else                   gp[k] = fmaf(xn[i], -xgj, gp[k]);
                }
                if ((ma | mb) == 15) {                 // join support
                    const int k = M2I(ma & mb);
                    if (jsign(ma, mb) > 0) jn[k] = fmaf(xn[i],  xgj, jn[k]);
                    else                   jn[k] = fmaf(xn[i], -xgj, jn[k]);
                }
            }
        }

        // ---- output linears (x15 folded into join weights) + residual ----
        const float4 wga = *reinterpret_cast<const float4*>(wg);
        const float  wgb = wg[4];
        const float4 vga = *reinterpret_cast<const float4*>(vg);
        const float4 wja = *reinterpret_cast<const float4*>(wj);
        const float  wjb = wj[4];
        const float4 vja = *reinterpret_cast<const float4*>(vj);

        const float x15 = xn[15];
        const float WG[5] = { wga.x, wga.y, wga.z, wga.w, wgb };
        const float VG[4] = { vga.x, vga.y, vga.z, vga.w };
        const float WJ[5] = { wja.x * x15, wja.y * x15, wja.z * x15,
                              wja.w * x15, wjb * x15 };
        const float VJ[4] = { vja.x * x15, vja.y * x15, vja.z * x15, vja.w * x15 };

        #pragma unroll
        for (int d = 0; d < 16; d++) {
            const int m = I2M(d);
            const int g = pc4(m);
            float v = xn[d] * nrm;               // residual: original x[d]
            v = fmaf(WG[g], gp[d], v);
            v = fmaf(WJ[g], jn[d], v);
            if ((m & 1) && g < 4) {
                const int sidx = M2I(m ^ 1);
                v = fmaf(VG[g], gp[sidx], v);
                v = fmaf(VJ[g], jn[sidx], v);
            }
            o[d] = v;
        }
        o[0] += bg[0] + bj[0];

        // write own-token slots back into smem (no hazard: slots are private)
        stage[swz(tid, 0)] = make_float4(o[0],  o[1],  o[2],  o[3]);
        stage[swz(tid, 1)] = make_float4(o[4],  o[5],  o[6],  o[7]);
        stage[swz(tid, 2)] = make_float4(o[8],  o[9],  o[10], o[11]);
        stage[swz(tid, 3)] = make_float4(o[12], o[13], o[14], o[15]);
    }
    __syncthreads();

    // ---- coalesced store from swizzled smem ----
    #pragma unroll
    for (int k = 0; k < 4; k++) {
        int f = tid + k * TOK_PER_BLK;
        if (f < nf4) {
            int tt = f >> 2, c = f & 3;
            out4[f] = stage[swz(tt, c)];
        }
    }
}

extern "C" void kernel_launch(void* const* d_in, const int* in_sizes, int n_in,
                              void* d_out, int out_size)
{
    const float* x  = (const float*)d_in[0];
    const float* w1 = (const float*)d_in[1];
    const float* v1 = (const float*)d_in[2];
    const float* b1 = (const float*)d_in[3];
    const float* wg = (const float*)d_in[4];
    const float* vg = (const float*)d_in[5];
    const float* bg = (const float*)d_in[6];
    const float* wj = (const float*)d_in[7];
    const float* vj = (const float*)d_in[8];
    const float* bj = (const float*)d_in[9];

    const int ntok   = in_sizes[0] / 16;
    const int blocks = (ntok + TOK_PER_BLK - 1) / TOK_PER_BLK;

    mvffn_kernel<<<blocks, TOK_PER_BLK>>>(x, w1, v1, b1, wg, vg, bg, wj, vj, bj,
                                          (float*)d_out, ntok);
}